// round 1
// baseline (speedup 1.0000x reference)
#include <cuda_runtime.h>
#include <math.h>

#define T_STEPS 512
#define BATCH   128
#define IN_DIM  64
#define HID     1024
#define OUT_DIM 64
#define NBLK    128
#define NTHR    256
#define JT      8
#define KC      32

// Persistent buffers (device globals -- no allocation in kernel_launch).
__device__ float g_h1[(size_t)T_STEPS * BATCH * HID];   // layer0 output, overwritten by layer1 output
__device__ float g_hbuf[2][BATCH * HID];                // double-buffered hidden state
__device__ volatile unsigned g_bar_gen;
__device__ unsigned g_bar_cnt;

__device__ __forceinline__ void grid_bar() {
    __threadfence();          // make this thread's global writes visible (L2)
    __syncthreads();
    if (threadIdx.x == 0) {
        unsigned gen = g_bar_gen;
        if (atomicAdd(&g_bar_cnt, 1u) == (unsigned)(NBLK - 1)) {
            g_bar_cnt = 0u;
            __threadfence();
            g_bar_gen = gen + 1u;
        } else {
            while (g_bar_gen == gen) { /* spin on L2 */ }
        }
        __threadfence();
    }
    __syncthreads();
}

#define FMA12(ACCN)                                                                   \
    {                                                                                 \
        float4 a = *(const float4*)(sA + kk * 132 + brow);                            \
        float wr = sWk[kk * 24 + jl];                                                 \
        float wz = sWk[kk * 24 + 8 + jl];                                             \
        float wn = sWk[kk * 24 + 16 + jl];                                            \
        ar[0] = fmaf(a.x, wr, ar[0]); ar[1] = fmaf(a.y, wr, ar[1]);                   \
        ar[2] = fmaf(a.z, wr, ar[2]); ar[3] = fmaf(a.w, wr, ar[3]);                   \
        az[0] = fmaf(a.x, wz, az[0]); az[1] = fmaf(a.y, wz, az[1]);                   \
        az[2] = fmaf(a.z, wz, az[2]); az[3] = fmaf(a.w, wz, az[3]);                   \
        ACCN[0] = fmaf(a.x, wn, ACCN[0]); ACCN[1] = fmaf(a.y, wn, ACCN[1]);           \
        ACCN[2] = fmaf(a.z, wn, ACCN[2]); ACCN[3] = fmaf(a.w, wn, ACCN[3]);           \
    }

// One persistent kernel runs the full 512-step recurrence of one GRU layer.
// Block b owns hidden units [b*8, b*8+8): its 24 weight columns (r,z,n) over the
// full K = KIN+HID live in shared memory for the whole kernel.
template <int KIN, bool IS_L0>
__global__ void __launch_bounds__(NTHR, 1)
gru_layer(const float* __restrict__ x_in,
          const float* __restrict__ w_ih, const float* __restrict__ w_hh,
          const float* __restrict__ b_ih, const float* __restrict__ b_hh)
{
    constexpr int KTOT   = KIN + HID;
    constexpr int NCH    = KTOT / KC;
    constexpr int NCH_IN = KIN / KC;

    extern __shared__ float smem[];
    float* sW = smem;                 // [KTOT][24]  (k-major; [g*8+jl] within row)
    float* sA = smem + KTOT * 24;     // [KC][132]   (transposed activation chunk)

    const int tid  = threadIdx.x;
    const int bid  = blockIdx.x;
    const int j0   = bid * JT;
    const int jl   = tid & 7;         // hidden unit within block
    const int j    = j0 + jl;
    const int brow = (tid >> 3) << 2; // batch row base (0..124)

    // ---- load persistent weight tile into smem (once) ----
    for (int idx = tid; idx < KTOT * 24; idx += NTHR) {
        int k  = idx / 24;
        int r  = idx - k * 24;
        int g  = r >> 3;
        int jj = r & 7;
        int row = g * HID + j0 + jj;
        sW[idx] = (k < KIN) ? w_ih[(size_t)row * KIN + k]
                            : w_hh[(size_t)row * HID + (k - KIN)];
    }

    const float br_b  = b_ih[j] + b_hh[j];
    const float bz_b  = b_ih[HID + j] + b_hh[HID + j];
    const float bin_b = b_ih[2 * HID + j];
    const float bhn_b = b_hh[2 * HID + j];

    // h0 = 0
    for (int idx = bid * NTHR + tid; idx < BATCH * HID; idx += NBLK * NTHR)
        g_hbuf[0][idx] = 0.0f;

    grid_bar();

    const int bload = tid >> 1;        // batch row this thread stages
    const int kh    = (tid & 1) << 4;  // k-offset (0 or 16) this thread stages

    for (int t = 0; t < T_STEPS; ++t) {
        const float* hprev = g_hbuf[t & 1];
        float*       hnext = g_hbuf[(t + 1) & 1];
        const float* seq_in = IS_L0 ? (x_in + (size_t)t * BATCH * KIN)
                                    : (g_h1 + (size_t)t * BATCH * HID);

        float ar[4]  = {0.f, 0.f, 0.f, 0.f};
        float az[4]  = {0.f, 0.f, 0.f, 0.f};
        float ani[4] = {0.f, 0.f, 0.f, 0.f};   // input-side n accumulator
        float anh[4] = {0.f, 0.f, 0.f, 0.f};   // hidden-side n accumulator

        // prefetch chunk 0 (always input segment: NCH_IN >= 2)
        float4 pf0, pf1, pf2, pf3;
        {
            const float* p = seq_in + (size_t)bload * KIN + kh;
            pf0 = __ldcg((const float4*)(p + 0));
            pf1 = __ldcg((const float4*)(p + 4));
            pf2 = __ldcg((const float4*)(p + 8));
            pf3 = __ldcg((const float4*)(p + 12));
        }

        #pragma unroll 1
        for (int c = 0; c < NCH; ++c) {
            __syncthreads();   // previous chunk fully consumed
            {
                float* d = sA + bload;
                d[(kh + 0)  * 132] = pf0.x; d[(kh + 1)  * 132] = pf0.y;
                d[(kh + 2)  * 132] = pf0.z; d[(kh + 3)  * 132] = pf0.w;
                d[(kh + 4)  * 132] = pf1.x; d[(kh + 5)  * 132] = pf1.y;
                d[(kh + 6)  * 132] = pf1.z; d[(kh + 7)  * 132] = pf1.w;
                d[(kh + 8)  * 132] = pf2.x; d[(kh + 9)  * 132] = pf2.y;
                d[(kh + 10) * 132] = pf2.z; d[(kh + 11) * 132] = pf2.w;
                d[(kh + 12) * 132] = pf3.x; d[(kh + 13) * 132] = pf3.y;
                d[(kh + 14) * 132] = pf3.z; d[(kh + 15) * 132] = pf3.w;
            }
            if (c + 1 < NCH) {  // prefetch next chunk while this one computes
                const int cn = c + 1;
                const float* src; int ld, kloc;
                if (cn < NCH_IN) { src = seq_in; ld = KIN; kloc = cn * KC; }
                else             { src = hprev;  ld = HID; kloc = (cn - NCH_IN) * KC; }
                const float* p = src + (size_t)bload * ld + kloc + kh;
                pf0 = __ldcg((const float4*)(p + 0));
                pf1 = __ldcg((const float4*)(p + 4));
                pf2 = __ldcg((const float4*)(p + 8));
                pf3 = __ldcg((const float4*)(p + 12));
            }
            __syncthreads();   // chunk staged
            const float* sWk = sW + c * (KC * 24);
            if (c < NCH_IN) {
                #pragma unroll 8
                for (int kk = 0; kk < KC; ++kk) FMA12(ani)
            } else {
                #pragma unroll 8
                for (int kk = 0; kk < KC; ++kk) FMA12(anh)
            }
        }

        // ---- gate math + h writeback ----
        float hv[4];
        #pragma unroll
        for (int b = 0; b < 4; ++b) {
            float hp = __ldcg(hprev + (size_t)(brow + b) * HID + j);
            float rg = 1.0f / (1.0f + expf(-(ar[b] + br_b)));
            float zg = 1.0f / (1.0f + expf(-(az[b] + bz_b)));
            float ng = tanhf(ani[b] + bin_b + rg * (anh[b] + bhn_b));
            float h  = (1.0f - zg) * ng + zg * hp;
            hnext[(size_t)(brow + b) * HID + j] = h;
            if (IS_L0)
                g_h1[(size_t)t * BATCH * HID + (size_t)(brow + b) * HID + j] = h;
            hv[b] = h;
        }

        grid_bar();

        if (!IS_L0) {
            // everyone has finished reading g_h1[t]; overwrite it with h2[t]
            #pragma unroll
            for (int b = 0; b < 4; ++b)
                g_h1[(size_t)t * BATCH * HID + (size_t)(brow + b) * HID + j] = hv[b];
        }
    }
}

// out[t,b,o] = h2[t,b,:] . w_lin[o,:] + b_lin[o].  64x64 tile per block, K=1024.
__global__ void __launch_bounds__(256)
out_linear(const float* __restrict__ w_lin, const float* __restrict__ b_lin,
           float* __restrict__ out)
{
    __shared__ float sA[16][68];
    __shared__ float sB[16][68];
    const int tid = threadIdx.x;
    const size_t rb = (size_t)blockIdx.x * 64;
    const int ty = tid >> 4;
    const int tx = tid & 15;

    const int li   = tid * 4;
    const int srow = li >> 4;   // 0..63
    const int skk  = li & 15;   // 0,4,8,12

    float acc[4][4] = {};

    for (int kc = 0; kc < HID; kc += 16) {
        __syncthreads();
        float4 va = __ldcg((const float4*)(g_h1 + (rb + srow) * HID + kc + skk));
        sA[skk + 0][srow] = va.x; sA[skk + 1][srow] = va.y;
        sA[skk + 2][srow] = va.z; sA[skk + 3][srow] = va.w;
        float4 vb = *(const float4*)(w_lin + (size_t)srow * HID + kc + skk);
        sB[skk + 0][srow] = vb.x; sB[skk + 1][srow] = vb.y;
        sB[skk + 2][srow] = vb.z; sB[skk + 3][srow] = vb.w;
        __syncthreads();
        #pragma unroll
        for (int kk = 0; kk < 16; ++kk) {
            float4 a = *(const float4*)&sA[kk][ty * 4];
            float4 b = *(const float4*)&sB[kk][tx * 4];
            acc[0][0] = fmaf(a.x, b.x, acc[0][0]); acc[0][1] = fmaf(a.x, b.y, acc[0][1]);
            acc[0][2] = fmaf(a.x, b.z, acc[0][2]); acc[0][3] = fmaf(a.x, b.w, acc[0][3]);
            acc[1][0] = fmaf(a.y, b.x, acc[1][0]); acc[1][1] = fmaf(a.y, b.y, acc[1][1]);
            acc[1][2] = fmaf(a.y, b.z, acc[1][2]); acc[1][3] = fmaf(a.y, b.w, acc[1][3]);
            acc[2][0] = fmaf(a.z, b.x, acc[2][0]); acc[2][1] = fmaf(a.z, b.y, acc[2][1]);
            acc[2][2] = fmaf(a.z, b.z, acc[2][2]); acc[2][3] = fmaf(a.z, b.w, acc[2][3]);
            acc[3][0] = fmaf(a.w, b.x, acc[3][0]); acc[3][1] = fmaf(a.w, b.y, acc[3][1]);
            acc[3][2] = fmaf(a.w, b.z, acc[3][2]); acc[3][3] = fmaf(a.w, b.w, acc[3][3]);
        }
    }

    #pragma unroll
    for (int i = 0; i < 4; ++i) {
        float4 o4;
        o4.x = acc[i][0] + b_lin[tx * 4 + 0];
        o4.y = acc[i][1] + b_lin[tx * 4 + 1];
        o4.z = acc[i][2] + b_lin[tx * 4 + 2];
        o4.w = acc[i][3] + b_lin[tx * 4 + 3];
        *(float4*)(out + (rb + ty * 4 + i) * OUT_DIM + tx * 4) = o4;
    }
}

extern "C" void kernel_launch(void* const* d_in, const int* in_sizes, int n_in,
                              void* d_out, int out_size)
{
    const float* x     = (const float*)d_in[0];
    const float* w_ih0 = (const float*)d_in[1];
    const float* w_hh0 = (const float*)d_in[2];
    const float* b_ih0 = (const float*)d_in[3];
    const float* b_hh0 = (const float*)d_in[4];
    const float* w_ih1 = (const float*)d_in[5];
    const float* w_hh1 = (const float*)d_in[6];
    const float* b_ih1 = (const float*)d_in[7];
    const float* b_hh1 = (const float*)d_in[8];
    const float* w_lin = (const float*)d_in[9];
    const float* b_lin = (const float*)d_in[10];
    float* out = (float*)d_out;
    (void)in_sizes; (void)n_in; (void)out_size;

    const int smem0 = (IN_DIM + HID) * 24 * 4 + KC * 132 * 4;  // 121,344 B
    const int smem1 = (HID + HID)    * 24 * 4 + KC * 132 * 4;  // 213,504 B

    cudaFuncSetAttribute(gru_layer<IN_DIM, true>,
                         cudaFuncAttributeMaxDynamicSharedMemorySize, smem0);
    cudaFuncSetAttribute(gru_layer<HID, false>,
                         cudaFuncAttributeMaxDynamicSharedMemorySize, smem1);

    gru_layer<IN_DIM, true><<<NBLK, NTHR, smem0>>>(x, w_ih0, w_hh0, b_ih0, b_hh0);
    gru_layer<HID, false><<<NBLK, NTHR, smem1>>>(nullptr, w_ih1, w_hh1, b_ih1, b_hh1);
    out_linear<<<(T_STEPS * BATCH) / 64, 256>>>(w_lin, b_lin, out);
}

// round 2
// speedup vs baseline: 1.3211x; 1.3211x over previous
#include <cuda_runtime.h>
#include <math.h>

#define T_STEPS 512
#define BATCH   128
#define IN_DIM  64
#define HID     1024
#define OUT_DIM 64
#define GATES   (3 * HID)
#define MROWS   (T_STEPS * BATCH)   // 65536
#define NBLK    128
#define NTHR    256

typedef unsigned long long u64;

// Persistent scratch (device globals -- no allocation in kernel_launch).
__device__ float g_gi[(size_t)MROWS * GATES];  // input-side gates (reused by both layers)
__device__ float g_h1[(size_t)MROWS * HID];    // layer0 output, then overwritten with layer1 output
__device__ float g_hT[2][HID * BATCH];         // double-buffered hidden state, TRANSPOSED [H][B]
__device__ volatile unsigned g_bar_gen;
__device__ unsigned g_bar_cnt;

// ---------- f32x2 helpers ----------
__device__ __forceinline__ void fma2(u64 &d, u64 a, u64 b) {
    asm("fma.rn.f32x2 %0, %1, %2, %0;" : "+l"(d) : "l"(a), "l"(b));
}
__device__ __forceinline__ u64 dup2(float x) {
    u64 r; asm("mov.b64 %0, {%1, %1};" : "=l"(r) : "f"(x)); return r;
}
__device__ __forceinline__ float2 unpk(u64 v) {
    float2 r; asm("mov.b64 {%0, %1}, %2;" : "=f"(r.x), "=f"(r.y) : "l"(v)); return r;
}
__device__ __forceinline__ ulonglong2 ldcg_u64x2(const void* p) {
    ulonglong2 v;
    asm volatile("ld.global.cg.v2.u64 {%0, %1}, [%2];"
                 : "=l"(v.x), "=l"(v.y) : "l"(p));
    return v;
}
__device__ __forceinline__ float4 ldcg_f32x4(const void* p) {
    float4 v;
    asm volatile("ld.global.cg.v4.f32 {%0, %1, %2, %3}, [%4];"
                 : "=f"(v.x), "=f"(v.y), "=f"(v.z), "=f"(v.w) : "l"(p));
    return v;
}
__device__ __forceinline__ float ldcg_f32(const void* p) {
    float v;
    asm volatile("ld.global.cg.f32 %0, [%1];" : "=f"(v) : "l"(p));
    return v;
}

__device__ __forceinline__ void grid_bar() {
    __threadfence();
    __syncthreads();
    if (threadIdx.x == 0) {
        unsigned gen = g_bar_gen;
        if (atomicAdd(&g_bar_cnt, 1u) == (unsigned)(NBLK - 1)) {
            g_bar_cnt = 0u;
            __threadfence();
            g_bar_gen = gen + 1u;
        } else {
            while (g_bar_gen == gen) { }
        }
        __threadfence();
    }
    __syncthreads();
}

// ============================================================================
// Recurrence: h_t = GRU(h_{t-1}) with input-side gates precomputed in g_gi.
// Block b owns 8 hidden units; their hidden weights (duplicated for f32x2)
// live persistently in smem (192 KB). Activations are read straight from L2
// (transposed h layout => 64B broadcast per warp per k). No syncs in k-loop.
// ============================================================================
__global__ void __launch_bounds__(NTHR, 1)
gru_rec(const float* __restrict__ w_hh, const float* __restrict__ b_ih,
        const float* __restrict__ b_hh)
{
    extern __shared__ float smem[];
    float* sWrz = smem;              // [HID][8 units][4] = {wr,wr,wz,wz}   128 KB
    float* sWn  = smem + HID * 32;   // [HID][8 units][2] = {wn,wn}          64 KB

    const int tid  = threadIdx.x;
    const int bid  = blockIdx.x;
    const int j0   = bid * 8;
    const int jl   = tid & 7;
    const int j    = j0 + jl;
    const int brow = (tid >> 3) << 2;  // batch base, 0..124

    // fill persistent weight tile (coalesced over k)
    for (int idx = tid; idx < HID * 8; idx += NTHR) {
        int u = idx >> 10;
        int k = idx & 1023;
        int row = j0 + u;
        float wr = w_hh[(size_t)row * HID + k];
        float wz = w_hh[(size_t)(HID + row) * HID + k];
        float wn = w_hh[(size_t)(2 * HID + row) * HID + k];
        float* p = sWrz + k * 32 + u * 4;
        p[0] = wr; p[1] = wr; p[2] = wz; p[3] = wz;
        float* q = sWn + k * 16 + u * 2;
        q[0] = wn; q[1] = wn;
    }

    const float br_b  = b_ih[j] + b_hh[j];
    const float bz_b  = b_ih[HID + j] + b_hh[HID + j];
    const float bin_b = b_ih[2 * HID + j];
    const float bhn_b = b_hh[2 * HID + j];

    // h0 = 0
    for (int idx = bid * NTHR + tid; idx < HID * BATCH; idx += NBLK * NTHR)
        g_hT[0][idx] = 0.0f;

    grid_bar();

    for (int t = 0; t < T_STEPS; ++t) {
        const float* hT  = g_hT[t & 1];
        float*       hTn = g_hT[(t + 1) & 1];

        // prefetch gi + h_prev needed for gate math (consumed after k-loop)
        const float* gi = g_gi + (size_t)t * BATCH * GATES;
        float gir[4], giz[4], gin[4];
        #pragma unroll
        for (int i = 0; i < 4; ++i) {
            const float* gp = gi + (size_t)(brow + i) * GATES + j;
            gir[i] = ldcg_f32(gp);
            giz[i] = ldcg_f32(gp + HID);
            gin[i] = ldcg_f32(gp + 2 * HID);
        }
        float4 hp = ldcg_f32x4(hT + j * BATCH + brow);

        u64 ar0 = 0, ar1 = 0, az0 = 0, az1 = 0, an0 = 0, an1 = 0;
        const float* ap = hT + brow;

        #pragma unroll 8
        for (int k = 0; k < HID; ++k) {
            ulonglong2 a   = ldcg_u64x2(ap + (size_t)k * BATCH);
            ulonglong2 wrz = *(const ulonglong2*)(sWrz + k * 32 + jl * 4);
            u64        wn  = *(const u64*)(sWn + k * 16 + jl * 2);
            fma2(ar0, a.x, wrz.x); fma2(ar1, a.y, wrz.x);
            fma2(az0, a.x, wrz.y); fma2(az1, a.y, wrz.y);
            fma2(an0, a.x, wn);    fma2(an1, a.y, wn);
        }

        float2 r01 = unpk(ar0), r23 = unpk(ar1);
        float2 z01 = unpk(az0), z23 = unpk(az1);
        float2 n01 = unpk(an0), n23 = unpk(an1);
        float rr[4]  = {r01.x, r01.y, r23.x, r23.y};
        float zz[4]  = {z01.x, z01.y, z23.x, z23.y};
        float nn[4]  = {n01.x, n01.y, n23.x, n23.y};
        float hpv[4] = {hp.x, hp.y, hp.z, hp.w};
        float hv[4];
        #pragma unroll
        for (int i = 0; i < 4; ++i) {
            float rg = 1.0f / (1.0f + expf(-(gir[i] + rr[i] + br_b)));
            float zg = 1.0f / (1.0f + expf(-(giz[i] + zz[i] + bz_b)));
            float ng = tanhf(gin[i] + bin_b + rg * (nn[i] + bhn_b));
            hv[i] = (1.0f - zg) * ng + zg * hpv[i];
        }

        float4 ho = make_float4(hv[0], hv[1], hv[2], hv[3]);
        *(float4*)(hTn + j * BATCH + brow) = ho;
        // layer output in [T][B][H] (layer0: h1 for the gi1 GEMM; layer1: h2 for out_linear)
        float* o = g_h1 + (size_t)t * BATCH * HID + j;
        #pragma unroll
        for (int i = 0; i < 4; ++i) o[(size_t)(brow + i) * HID] = hv[i];

        grid_bar();
    }
}

// ============================================================================
// C[m][n] = sum_k A[m][k] * B[n][k]   (both k-contiguous), f32x2 inner.
// 128x128 tile / block, 256 threads, thread tile 8x8, KC=16, single-buffer
// smem with register prefetch of the next chunk. M,N multiples of 128; K of 16.
// ============================================================================
#define GKC 16
__global__ void __launch_bounds__(256)
gemm_tn_f32x2(const float* __restrict__ A, const float* __restrict__ B,
              float* __restrict__ C, int M, int N, int K)
{
    __shared__ float sA[GKC][132];
    __shared__ float sB[GKC][132];
    const int tid = threadIdx.x;
    const int m0  = blockIdx.y * 128;
    const int n0  = blockIdx.x * 128;
    const int ty  = tid >> 4, tx = tid & 15;

    const int sr = tid >> 1;         // staging row 0..127
    const int sk = (tid & 1) * 8;    // staging k offset 0/8

    u64 acc[4][8];
    #pragma unroll
    for (int p = 0; p < 4; ++p)
        #pragma unroll
        for (int c = 0; c < 8; ++c) acc[p][c] = 0ull;

    const float* Ag = A + (size_t)(m0 + sr) * K + sk;
    const float* Bg = B + (size_t)(n0 + sr) * K + sk;

    float4 a0 = ldcg_f32x4(Ag);
    float4 a1 = ldcg_f32x4(Ag + 4);
    float4 b0 = ldcg_f32x4(Bg);
    float4 b1 = ldcg_f32x4(Bg + 4);

    for (int kc = 0; kc < K; kc += GKC) {
        sA[sk + 0][sr] = a0.x; sA[sk + 1][sr] = a0.y;
        sA[sk + 2][sr] = a0.z; sA[sk + 3][sr] = a0.w;
        sA[sk + 4][sr] = a1.x; sA[sk + 5][sr] = a1.y;
        sA[sk + 6][sr] = a1.z; sA[sk + 7][sr] = a1.w;
        sB[sk + 0][sr] = b0.x; sB[sk + 1][sr] = b0.y;
        sB[sk + 2][sr] = b0.z; sB[sk + 3][sr] = b0.w;
        sB[sk + 4][sr] = b1.x; sB[sk + 5][sr] = b1.y;
        sB[sk + 6][sr] = b1.z; sB[sk + 7][sr] = b1.w;
        if (kc + GKC < K) {
            Ag += GKC; Bg += GKC;
            a0 = ldcg_f32x4(Ag);
            a1 = ldcg_f32x4(Ag + 4);
            b0 = ldcg_f32x4(Bg);
            b1 = ldcg_f32x4(Bg + 4);
        }
        __syncthreads();

        #pragma unroll
        for (int kk = 0; kk < GKC; ++kk) {
            ulonglong2 aa = *(const ulonglong2*)(&sA[kk][ty * 8]);      // rows 0-3 (2 pairs)
            ulonglong2 ab = *(const ulonglong2*)(&sA[kk][ty * 8 + 4]);  // rows 4-7
            float4 bv0 = *(const float4*)(&sB[kk][tx * 8]);
            float4 bv1 = *(const float4*)(&sB[kk][tx * 8 + 4]);
            float bs[8] = {bv0.x, bv0.y, bv0.z, bv0.w, bv1.x, bv1.y, bv1.z, bv1.w};
            #pragma unroll
            for (int c = 0; c < 8; ++c) {
                u64 bd = dup2(bs[c]);
                fma2(acc[0][c], aa.x, bd);
                fma2(acc[1][c], aa.y, bd);
                fma2(acc[2][c], ab.x, bd);
                fma2(acc[3][c], ab.y, bd);
            }
        }
        __syncthreads();
    }

    #pragma unroll
    for (int p = 0; p < 4; ++p) {
        float2 v[8];
        #pragma unroll
        for (int c = 0; c < 8; ++c) v[c] = unpk(acc[p][c]);
        int row0 = m0 + ty * 8 + p * 2;
        float* c0 = C + (size_t)row0 * N + n0 + tx * 8;
        float* c1 = c0 + N;
        *(float4*)(c0)     = make_float4(v[0].x, v[1].x, v[2].x, v[3].x);
        *(float4*)(c0 + 4) = make_float4(v[4].x, v[5].x, v[6].x, v[7].x);
        *(float4*)(c1)     = make_float4(v[0].y, v[1].y, v[2].y, v[3].y);
        *(float4*)(c1 + 4) = make_float4(v[4].y, v[5].y, v[6].y, v[7].y);
    }
}

// ============================================================================
// out[t,b,o] = h2[t,b,:] . w_lin[o,:] + b_lin[o] (h2 lives in g_h1)
// ============================================================================
__global__ void __launch_bounds__(256)
out_linear(const float* __restrict__ w_lin, const float* __restrict__ b_lin,
           float* __restrict__ out)
{
    __shared__ float sA[16][68];
    __shared__ float sB[16][68];
    const int tid = threadIdx.x;
    const size_t rb = (size_t)blockIdx.x * 64;
    const int ty = tid >> 4;
    const int tx = tid & 15;

    const int li   = tid * 4;
    const int srow = li >> 4;
    const int skk  = li & 15;

    float acc[4][4] = {};

    for (int kc = 0; kc < HID; kc += 16) {
        __syncthreads();
        float4 va = ldcg_f32x4(g_h1 + (rb + srow) * HID + kc + skk);
        sA[skk + 0][srow] = va.x; sA[skk + 1][srow] = va.y;
        sA[skk + 2][srow] = va.z; sA[skk + 3][srow] = va.w;
        float4 vb = *(const float4*)(w_lin + (size_t)srow * HID + kc + skk);
        sB[skk + 0][srow] = vb.x; sB[skk + 1][srow] = vb.y;
        sB[skk + 2][srow] = vb.z; sB[skk + 3][srow] = vb.w;
        __syncthreads();
        #pragma unroll
        for (int kk = 0; kk < 16; ++kk) {
            float4 a = *(const float4*)&sA[kk][ty * 4];
            float4 b = *(const float4*)&sB[kk][tx * 4];
            acc[0][0] = fmaf(a.x, b.x, acc[0][0]); acc[0][1] = fmaf(a.x, b.y, acc[0][1]);
            acc[0][2] = fmaf(a.x, b.z, acc[0][2]); acc[0][3] = fmaf(a.x, b.w, acc[0][3]);
            acc[1][0] = fmaf(a.y, b.x, acc[1][0]); acc[1][1] = fmaf(a.y, b.y, acc[1][1]);
            acc[1][2] = fmaf(a.y, b.z, acc[1][2]); acc[1][3] = fmaf(a.y, b.w, acc[1][3]);
            acc[2][0] = fmaf(a.z, b.x, acc[2][0]); acc[2][1] = fmaf(a.z, b.y, acc[2][1]);
            acc[2][2] = fmaf(a.z, b.z, acc[2][2]); acc[2][3] = fmaf(a.z, b.w, acc[2][3]);
            acc[3][0] = fmaf(a.w, b.x, acc[3][0]); acc[3][1] = fmaf(a.w, b.y, acc[3][1]);
            acc[3][2] = fmaf(a.w, b.z, acc[3][2]); acc[3][3] = fmaf(a.w, b.w, acc[3][3]);
        }
    }

    #pragma unroll
    for (int i = 0; i < 4; ++i) {
        float4 o4;
        o4.x = acc[i][0] + b_lin[tx * 4 + 0];
        o4.y = acc[i][1] + b_lin[tx * 4 + 1];
        o4.z = acc[i][2] + b_lin[tx * 4 + 2];
        o4.w = acc[i][3] + b_lin[tx * 4 + 3];
        *(float4*)(out + (rb + ty * 4 + i) * OUT_DIM + tx * 4) = o4;
    }
}

extern "C" void kernel_launch(void* const* d_in, const int* in_sizes, int n_in,
                              void* d_out, int out_size)
{
    const float* x     = (const float*)d_in[0];
    const float* w_ih0 = (const float*)d_in[1];
    const float* w_hh0 = (const float*)d_in[2];
    const float* b_ih0 = (const float*)d_in[3];
    const float* b_hh0 = (const float*)d_in[4];
    const float* w_ih1 = (const float*)d_in[5];
    const float* w_hh1 = (const float*)d_in[6];
    const float* b_ih1 = (const float*)d_in[7];
    const float* b_hh1 = (const float*)d_in[8];
    const float* w_lin = (const float*)d_in[9];
    const float* b_lin = (const float*)d_in[10];
    float* out = (float*)d_out;
    (void)in_sizes; (void)n_in; (void)out_size;

    float *gi_ptr, *h1_ptr;
    cudaGetSymbolAddress((void**)&gi_ptr, g_gi);
    cudaGetSymbolAddress((void**)&h1_ptr, g_h1);

    const int rec_smem = HID * 48 * 4;  // 196,608 B
    cudaFuncSetAttribute(gru_rec, cudaFuncAttributeMaxDynamicSharedMemorySize, rec_smem);

    dim3 ggrid(GATES / 128, MROWS / 128);   // (24, 512)

    // layer 0: input-side gates (K=64), then recurrence
    gemm_tn_f32x2<<<ggrid, 256>>>(x, w_ih0, gi_ptr, MROWS, GATES, IN_DIM);
    gru_rec<<<NBLK, NTHR, rec_smem>>>(w_hh0, b_ih0, b_hh0);

    // layer 1: input-side gates from h1 (K=1024), then recurrence
    gemm_tn_f32x2<<<ggrid, 256>>>(h1_ptr, w_ih1, gi_ptr, MROWS, GATES, HID);
    gru_rec<<<NBLK, NTHR, rec_smem>>>(w_hh1, b_ih1, b_hh1);

    // time-distributed linear on h2 (in g_h1)
    out_linear<<<(MROWS) / 64, 256>>>(w_lin, b_lin, out);
}